// round 11
// baseline (speedup 1.0000x reference)
#include <cuda_runtime.h>
#include <math.h>

// Problem constants
#define N_ROWS 32768
#define DIM    512
#define NSTAGES 8
#define NCODES 4096

// Tile config
#define BM 64
#define BN 64
#define BKC 64
// dynamic smem: A [DIM][BM] + B [BKC][BN]
#define SMEM_FLOATS (DIM*BM + BKC*BN)
#define SMEM_BYTES  (SMEM_FLOATS * 4)

__device__ float g_res[(size_t)N_ROWS * DIM];            // residual carry
__device__ float g_cbn[(size_t)NSTAGES * NCODES * DIM];  // normalized codebooks

// ---------------------------------------------------------------------------
// Normalize codebooks exactly as XLA:CPU does (strict IEEE, no fast-math):
//   S = sum_{k ascending} fadd(S, fmul(c_k, c_k))   (scalar sequential, NO fma)
//   n = max(sqrt_rn(S), 1e-12)
//   b_k = fdiv_rn(c_k, n)
// One THREAD per codeword (order must be strictly sequential).
// ---------------------------------------------------------------------------
__global__ void normalize_cb_kernel(const float* __restrict__ cb) {
    int cw = blockIdx.x * blockDim.x + threadIdx.x;
    if (cw >= NSTAGES * NCODES) return;
    const float* row = cb + (size_t)cw * DIM;
    float* orow = g_cbn + (size_t)cw * DIM;

    float S = 0.0f;
#pragma unroll 8
    for (int k = 0; k < DIM; k++) {
        float v = row[k];
        S = __fadd_rn(S, __fmul_rn(v, v));
    }
    float n = fmaxf(__fsqrt_rn(S), 1e-12f);
#pragma unroll 8
    for (int k = 0; k < DIM; k++) {
        orow[k] = __fdiv_rn(row[k], n);
    }
}

// ---------------------------------------------------------------------------
// Init: res = x (exact), hard = 0.
// ---------------------------------------------------------------------------
__global__ void init_kernel(const float* __restrict__ x, float* __restrict__ hard) {
    int i = blockIdx.x * blockDim.x + threadIdx.x;
    int stride = gridDim.x * blockDim.x;
    for (; i < N_ROWS * DIM; i += stride) {
        g_res[i] = x[i];
        hard[i] = 0.0f;
    }
}

// ---------------------------------------------------------------------------
// One RVQ stage. Each block owns BM=64 rows:
//   A) load res tile to SMEM transposed; per-row norm via STRICT sequential
//      scalar fp32 sum of squares (mul+add, no fma, ascending k) — matches
//      XLA:CPU reduce; then a = fdiv_rn(res, n) elementwise
//   B) stream normalized-codeword chunks of 64: single-accumulator fp32 FFMA
//      GEMM over strictly ascending k — matches Eigen gebp (fmla chain);
//      fused argmax, first-index tie-break
//   C) cross-thread argmax reduction, write ids
//   D) res -= cb[best]; hard += cb[best]  (elementwise, original codebook)
// ---------------------------------------------------------------------------
__global__ void __launch_bounds__(256, 1)
stage_kernel(const float* __restrict__ cb,      // original codebook [NCODES][DIM]
             const float* __restrict__ cbn,     // normalized codebook [NCODES][DIM]
             float* __restrict__ hard,          // [N_ROWS][DIM]
             float* __restrict__ ids_out,       // [N_ROWS][NSTAGES] as float, may be null
             int stage) {
    extern __shared__ float smem[];
    float* A_s = smem;                 // [k*64 + row], k in [0,512)
    float* B_s = smem + DIM * BM;      // [k*64 + cw],  k in [0,64)
    __shared__ int   winner[BM];
    __shared__ float rnorm[BM];

    const int t = threadIdx.x;
    const int tx = t & 15;             // codeword quad within chunk
    const int ty = t >> 4;             // row quad
    const int rowBase = blockIdx.x * BM;
    const int row = t & 63;
    const int ks = t >> 6;             // 4 K-slices of 128

    // ---- Phase A1: residual tile, transposed ----
    {
        const float4* rr = (const float4*)(g_res + (size_t)(rowBase + row) * DIM);
#pragma unroll 4
        for (int j = 0; j < 32; j++) {
            int k = ks * 128 + j * 4;
            float4 rv = rr[k >> 2];
            A_s[(k + 0) * BM + row] = rv.x;
            A_s[(k + 1) * BM + row] = rv.y;
            A_s[(k + 2) * BM + row] = rv.z;
            A_s[(k + 3) * BM + row] = rv.w;
        }
    }
    __syncthreads();

    // ---- Phase A2: strict sequential row norm (threads 0..63, one per row) ----
    if (t < BM) {
        float S = 0.0f;
#pragma unroll 8
        for (int k = 0; k < DIM; k++) {
            float v = A_s[k * BM + t];
            S = __fadd_rn(S, __fmul_rn(v, v));
        }
        rnorm[t] = fmaxf(__fsqrt_rn(S), 1e-12f);
    }
    __syncthreads();

    // ---- Phase A3: a = res / n, IEEE divide ----
    {
        float n = rnorm[row];
#pragma unroll 4
        for (int j = 0; j < 32; j++) {
            int k = ks * 128 + j * 4;
            A_s[(k + 0) * BM + row] = __fdiv_rn(A_s[(k + 0) * BM + row], n);
            A_s[(k + 1) * BM + row] = __fdiv_rn(A_s[(k + 1) * BM + row], n);
            A_s[(k + 2) * BM + row] = __fdiv_rn(A_s[(k + 2) * BM + row], n);
            A_s[(k + 3) * BM + row] = __fdiv_rn(A_s[(k + 3) * BM + row], n);
        }
    }
    __syncthreads();

    float bestS[4];
    int   bestI[4];
#pragma unroll
    for (int i = 0; i < 4; i++) { bestS[i] = -1e30f; bestI[i] = 0; }

    // ---- Phase B: stream normalized codeword chunks ----
    for (int cwb = 0; cwb < NCODES; cwb += BN) {
        float acc[4][4];
#pragma unroll
        for (int i = 0; i < 4; i++)
#pragma unroll
            for (int j = 0; j < 4; j++) acc[i][j] = 0.0f;

        for (int kc = 0; kc < DIM; kc += BKC) {
            // load B chunk [64 k x 64 cw], transposed store (lane=cw: conflict-free)
            {
                int cw = t & 63;
                int kq = t >> 6;       // 0..3
                const float* crow = cbn + (size_t)(cwb + cw) * DIM + kc;
#pragma unroll
                for (int j = 0; j < 4; j++) {
                    int k4 = kq + j * 4;   // 0..15
                    float4 v = *(const float4*)(crow + k4 * 4);
                    B_s[(k4 * 4 + 0) * BN + cw] = v.x;
                    B_s[(k4 * 4 + 1) * BN + cw] = v.y;
                    B_s[(k4 * 4 + 2) * BN + cw] = v.z;
                    B_s[(k4 * 4 + 3) * BN + cw] = v.w;
                }
            }
            __syncthreads();

            // single-accumulator FFMA chain over strictly ascending k
            // (nvcc -fmad contracts to FFMA == Eigen's fmla; order preserved
            //  because each acc is serially dependent and fast-math is off)
#pragma unroll 8
            for (int k = 0; k < BKC; k++) {
                float4 a = *(const float4*)(A_s + (kc + k) * BM + ty * 4);
                float4 b = *(const float4*)(B_s + k * BN + tx * 4);
                acc[0][0] += a.x * b.x; acc[0][1] += a.x * b.y;
                acc[0][2] += a.x * b.z; acc[0][3] += a.x * b.w;
                acc[1][0] += a.y * b.x; acc[1][1] += a.y * b.y;
                acc[1][2] += a.y * b.z; acc[1][3] += a.y * b.w;
                acc[2][0] += a.z * b.x; acc[2][1] += a.z * b.y;
                acc[2][2] += a.z * b.z; acc[2][3] += a.z * b.w;
                acc[3][0] += a.w * b.x; acc[3][1] += a.w * b.y;
                acc[3][2] += a.w * b.z; acc[3][3] += a.w * b.w;
            }
            __syncthreads();
        }

        // fused argmax (thread-local indices ascending; strict > keeps first)
#pragma unroll
        for (int j = 0; j < 4; j++) {
            int cw = cwb + tx * 4 + j;
#pragma unroll
            for (int i = 0; i < 4; i++) {
                float v = acc[i][j];
                if (v > bestS[i]) { bestS[i] = v; bestI[i] = cw; }
            }
        }
    }

    // ---- Phase C: cross-thread argmax reduction (reuse B_s) ----
    __syncthreads();
    float* redS = B_s;                       // [row*16 + tx]
    int*   redI = (int*)(B_s + BM * 16);     // [row*16 + tx]
#pragma unroll
    for (int i = 0; i < 4; i++) {
        redS[(ty * 4 + i) * 16 + tx] = bestS[i];
        redI[(ty * 4 + i) * 16 + tx] = bestI[i];
    }
    __syncthreads();
    if (t < BM) {
        float bs = redS[t * 16];
        int   bi = redI[t * 16];
#pragma unroll
        for (int j = 1; j < 16; j++) {
            float s2 = redS[t * 16 + j];
            int   i2 = redI[t * 16 + j];
            if (s2 > bs || (s2 == bs && i2 < bi)) { bs = s2; bi = i2; }
        }
        winner[t] = bi;
        if (ids_out)
            ids_out[(size_t)(rowBase + t) * NSTAGES + stage] = (float)bi;
    }
    __syncthreads();

    // ---- Phase D: res -= cb[winner]; hard += cb[winner] (elementwise) ----
    {
        int id = winner[row];
        const float4* q = (const float4*)(cb + (size_t)id * DIM);
        float4* hr = (float4*)(hard + (size_t)(rowBase + row) * DIM);
        float4* rr = (float4*)(g_res + (size_t)(rowBase + row) * DIM);
#pragma unroll 4
        for (int j = 0; j < 32; j++) {
            int k4 = ks * 32 + j;
            float4 qq = q[k4];
            float4 h = hr[k4];
            float4 r = rr[k4];
            h.x += qq.x; h.y += qq.y; h.z += qq.z; h.w += qq.w;
            r.x -= qq.x; r.y -= qq.y; r.z -= qq.z; r.w -= qq.w;
            hr[k4] = h;
            rr[k4] = r;
        }
    }
}

// ---------------------------------------------------------------------------
extern "C" void kernel_launch(void* const* d_in, const int* in_sizes, int n_in,
                              void* d_out, int out_size) {
    const float* x  = (const float*)d_in[0];        // [32768, 512]
    const float* cb = (const float*)d_in[1];        // [8, 4096, 512]
    float* out  = (float*)d_out;
    float* hard = out;                              // [32768, 512]
    float* ids  = nullptr;                          // [32768, 8] as float
    if (out_size >= N_ROWS * DIM + N_ROWS * NSTAGES)
        ids = out + (size_t)N_ROWS * DIM;

    cudaFuncSetAttribute(stage_kernel,
                         cudaFuncAttributeMaxDynamicSharedMemorySize, SMEM_BYTES);

    float* cbn_ptr = nullptr;
    cudaGetSymbolAddress((void**)&cbn_ptr, g_cbn);

    // normalize all codebooks (one thread per codeword, strict sequential)
    normalize_cb_kernel<<<(NSTAGES * NCODES + 255) / 256, 256>>>(cb);
    // res = x, hard = 0
    init_kernel<<<2048, 256>>>(x, hard);

    for (int s = 0; s < NSTAGES; s++) {
        stage_kernel<<<N_ROWS / BM, 256, SMEM_BYTES>>>(
            cb + (size_t)s * NCODES * DIM,
            cbn_ptr + (size_t)s * NCODES * DIM,
            hard, ids, s);
    }
}